// round 4
// baseline (speedup 1.0000x reference)
#include <cuda_runtime.h>
#include <cstdint>

// SparseToDense via full counting sort by voxel id, then one-thread-per-voxel
// register accumulation (NO atomics in the hot phase).
// out[b][f][x][y][z] += feats[n][f], out = (4,16,128,128,128) f32.

#define VOL      (128 * 128 * 128)
#define FEATS    16
#define VOXELS   (4 * VOL)          // 8388608
#define NMAX     2100000
#define SCAN_BLOCKS 2048
#define SCAN_CHUNK  4096            // 256 threads * 16 elems

__device__ int g_count[VOXELS];
__device__ int g_start[VOXELS + 1];
__device__ int g_cursor[VOXELS];    // after reorder: cursor[v] == end of run v
__device__ int g_blocksum[SCAN_BLOCKS];
__device__ int g_order[NMAX];

__device__ __forceinline__ bool voxel_of(const int4 c, unsigned& v)
{
    const unsigned x = (unsigned)c.y;
    const unsigned y = (unsigned)c.z;
    const unsigned z = (unsigned)c.w;
    if ((x >= 128u) | (y >= 128u) | (z >= 128u)) return false;
    v = ((unsigned)c.x << 21) | (x << 14) | (y << 7) | z;
    return true;
}

__global__ void zero_count_kernel()
{
    int i = blockIdx.x * blockDim.x + threadIdx.x;
    if (i < VOXELS / 4) ((int4*)g_count)[i] = make_int4(0, 0, 0, 0);
}

__global__ void __launch_bounds__(256)
hist_kernel(const int4* __restrict__ coords, int n)
{
    for (int i = blockIdx.x * blockDim.x + threadIdx.x; i < n;
         i += gridDim.x * blockDim.x) {
        unsigned v;
        if (voxel_of(__ldg(&coords[i]), v))
            asm volatile("red.global.add.u32 [%0], %1;"
                         :: "l"(g_count + v), "r"(1u) : "memory");
    }
}

// Phase A: per-block sums of 4096-elem chunks
__global__ void __launch_bounds__(256)
scan_a_kernel()
{
    __shared__ int s[256];
    const int t = threadIdx.x;
    const int4* p = (const int4*)(g_count + (size_t)blockIdx.x * SCAN_CHUNK) + t * 4;
    int sum = 0;
    #pragma unroll
    for (int k = 0; k < 4; k++) {
        int4 q = __ldg(p + k);
        sum += q.x + q.y + q.z + q.w;
    }
    s[t] = sum;
    __syncthreads();
    for (int off = 128; off > 0; off >>= 1) {
        if (t < off) s[t] += s[t + off];
        __syncthreads();
    }
    if (t == 0) g_blocksum[blockIdx.x] = s[0];
}

// Phase B: exclusive scan of the 2048 block sums (single block)
__global__ void scan_b_kernel()
{
    __shared__ int s[1024];
    const int t = threadIdx.x;
    const int a = g_blocksum[2 * t];
    const int b = g_blocksum[2 * t + 1];
    const int sum = a + b;
    s[t] = sum;
    __syncthreads();
    for (int off = 1; off < 1024; off <<= 1) {
        int x = (t >= off) ? s[t - off] : 0;
        __syncthreads();
        s[t] += x;
        __syncthreads();
    }
    const int excl = s[t] - sum;
    g_blocksum[2 * t]     = excl;
    g_blocksum[2 * t + 1] = excl + a;
    if (t == 1023) g_start[VOXELS] = s[1023];
}

// Phase C: local scan + global offset; writes g_start and g_cursor
__global__ void __launch_bounds__(256)
scan_c_kernel()
{
    __shared__ int s[256];
    const int t = threadIdx.x;
    const size_t base = (size_t)blockIdx.x * SCAN_CHUNK + (size_t)t * 16;
    int v[16];
    int sum = 0;
    const int4* p = (const int4*)(g_count + base);
    #pragma unroll
    for (int k = 0; k < 4; k++) {
        int4 q = __ldg(p + k);
        v[4*k+0] = q.x; v[4*k+1] = q.y; v[4*k+2] = q.z; v[4*k+3] = q.w;
        sum += q.x + q.y + q.z + q.w;
    }
    s[t] = sum;
    __syncthreads();
    for (int off = 1; off < 256; off <<= 1) {
        int x = (t >= off) ? s[t - off] : 0;
        __syncthreads();
        s[t] += x;
        __syncthreads();
    }
    int run = g_blocksum[blockIdx.x] + s[t] - sum;
    #pragma unroll
    for (int k = 0; k < 4; k++) {
        int4 o;
        o.x = run;           o.y = run + v[4*k];
        o.z = o.y + v[4*k+1]; o.w = o.z + v[4*k+2];
        run = o.w + v[4*k+3];
        ((int4*)(g_start  + base))[k] = o;
        ((int4*)(g_cursor + base))[k] = o;
    }
}

__global__ void __launch_bounds__(256)
reorder_kernel(const int4* __restrict__ coords, int n)
{
    for (int i = blockIdx.x * blockDim.x + threadIdx.x; i < n;
         i += gridDim.x * blockDim.x) {
        unsigned v;
        if (voxel_of(__ldg(&coords[i]), v)) {
            int pos = atomicAdd(&g_cursor[v], 1);
            g_order[pos] = i;
        }
    }
}

// One thread per voxel: register accumulation, smem staging, float4 writeback.
__global__ void __launch_bounds__(512)
scatter_kernel(const float4* __restrict__ feats, float* __restrict__ out)
{
    __shared__ float acc[FEATS * 512];
    const unsigned bin   = blockIdx.x;       // 16384 bins of 512 voxels
    const unsigned local = threadIdx.x;      // 0..511
    const unsigned v     = (bin << 9) | local;

    const int s = __ldg(&g_start[v]);
    const int e = __ldg(&g_cursor[v]);       // == start + count after reorder

    float a[FEATS];
    #pragma unroll
    for (int f = 0; f < FEATS; f++) a[f] = 0.f;

    for (int t = s; t < e; t++) {
        const int i = __ldg(&g_order[t]);
        const float4* fp = feats + (size_t)i * 4;
        float4 f0 = __ldg(fp + 0);
        float4 f1 = __ldg(fp + 1);
        float4 f2 = __ldg(fp + 2);
        float4 f3 = __ldg(fp + 3);
        a[0]  += f0.x; a[1]  += f0.y; a[2]  += f0.z; a[3]  += f0.w;
        a[4]  += f1.x; a[5]  += f1.y; a[6]  += f1.z; a[7]  += f1.w;
        a[8]  += f2.x; a[9]  += f2.y; a[10] += f2.z; a[11] += f2.w;
        a[12] += f3.x; a[13] += f3.y; a[14] += f3.z; a[15] += f3.w;
    }

    #pragma unroll
    for (int f = 0; f < FEATS; f++) acc[f * 512 + local] = a[f];
    __syncthreads();

    const unsigned b = bin >> 12;
    float* base = out + (size_t)b * FEATS * VOL + ((size_t)(bin & 4095u) << 9);

    #pragma unroll
    for (int k = 0; k < 4; k++) {
        const int idx = k * 512 + (int)threadIdx.x;  // 0..2047 float4 slots
        const int f = idx >> 7;                      // 128 float4 per feat
        const int w = idx & 127;
        float4 val = *(const float4*)&acc[f * 512 + w * 4];
        *(float4*)(base + (size_t)f * VOL + (size_t)w * 4) = val;
    }
}

extern "C" void kernel_launch(void* const* d_in, const int* in_sizes, int n_in,
                              void* d_out, int out_size)
{
    const int4*   coords = (const int4*)d_in[0];
    const float4* feats  = (const float4*)d_in[1];
    float*        out    = (float*)d_out;

    const int n = in_sizes[0] / 4;

    zero_count_kernel<<<VOXELS / 4 / 256, 256>>>();
    hist_kernel<<<1024, 256>>>(coords, n);
    scan_a_kernel<<<SCAN_BLOCKS, 256>>>();
    scan_b_kernel<<<1, 1024>>>();
    scan_c_kernel<<<SCAN_BLOCKS, 256>>>();
    reorder_kernel<<<1024, 256>>>(coords, n);
    scatter_kernel<<<VOXELS / 512, 512>>>(feats, out);
}

// round 6
// speedup vs baseline: 1.1189x; 1.1189x over previous
#include <cuda_runtime.h>
#include <cstdint>

// SparseToDense: counting sort to 16K (b,x,y/4) bins; scatter CTA does an
// in-smem counting sort by local voxel, then one-thread-per-voxel register
// accumulation with plain STS (no atomics on the hot path).
// out[b][f][x][y][z] += feats[n][f], out = (4,16,128,128,128) f32.

#define VOL    (128 * 128 * 128)
#define FEATS  16
#define NBINS  16384            // (b, x, y/4)
#define NMAX   2100000
#define CAP    192              // per-bin sorted-point capacity (avg ~93)

__device__ int g_bins[NBINS];
__device__ int g_cursor[NBINS];
__device__ int g_start[NBINS + 1];
__device__ unsigned g_binof[NMAX];   // per point: (bin<<9)|local, ~0u if invalid
__device__ unsigned g_order[NMAX];   // packed: (point_idx << 9) | local_voxel

__device__ __forceinline__ bool decode(const int4 c, unsigned& bin, unsigned& local)
{
    const unsigned x = (unsigned)c.y;
    const unsigned y = (unsigned)c.z;
    const unsigned z = (unsigned)c.w;
    if ((x >= 128u) | (y >= 128u) | (z >= 128u)) return false;
    bin   = ((((unsigned)c.x << 7) | x) << 5) | (y >> 2);
    local = ((y & 3u) << 7) | z;
    return true;
}

__global__ void zero_bins_kernel()
{
    int i = blockIdx.x * blockDim.x + threadIdx.x;
    if (i < NBINS) g_bins[i] = 0;
}

__global__ void __launch_bounds__(256)
hist_kernel(const int4* __restrict__ coords, int n)
{
    for (int i = blockIdx.x * blockDim.x + threadIdx.x; i < n;
         i += gridDim.x * blockDim.x) {
        unsigned bin, local;
        if (decode(__ldg(&coords[i]), bin, local)) {
            asm volatile("red.global.add.u32 [%0], %1;"
                         :: "l"(g_bins + bin), "r"(1u) : "memory");
            g_binof[i] = (bin << 9) | local;
        } else {
            g_binof[i] = ~0u;
        }
    }
}

__global__ void scan_kernel()
{
    __shared__ int s[1024];
    const int t = threadIdx.x;
    int v[16];
    int sum = 0;
    #pragma unroll
    for (int k = 0; k < 16; k++) { v[k] = g_bins[t * 16 + k]; sum += v[k]; }
    s[t] = sum;
    __syncthreads();
    for (int off = 1; off < 1024; off <<= 1) {
        int x = (t >= off) ? s[t - off] : 0;
        __syncthreads();
        s[t] += x;
        __syncthreads();
    }
    int run = s[t] - sum;
    #pragma unroll
    for (int k = 0; k < 16; k++) {
        g_start[t * 16 + k]  = run;
        g_cursor[t * 16 + k] = run;
        run += v[k];
    }
    if (t == 1023) g_start[NBINS] = run;
}

__global__ void __launch_bounds__(256)
reorder_kernel(int n)
{
    for (int i = blockIdx.x * blockDim.x + threadIdx.x; i < n;
         i += gridDim.x * blockDim.x) {
        const unsigned bl = g_binof[i];
        if (bl != ~0u) {
            int pos = atomicAdd(&g_cursor[bl >> 9], 1);
            g_order[pos] = ((unsigned)i << 9) | (bl & 511u);
        }
    }
}

__global__ void __launch_bounds__(256)
scatter_kernel(const float4* __restrict__ feats, float* __restrict__ out)
{
    __shared__ float    acc[FEATS * 512];   // [f][512]
    __shared__ int      cnt[512];           // hist, then cursors
    __shared__ int      soff[513];          // run starts
    __shared__ int      scrat[256];
    __shared__ unsigned spay[CAP];

    const unsigned bin = blockIdx.x;
    const int tid = threadIdx.x;
    const int start = g_start[bin];
    const int end   = g_start[bin + 1];

    #pragma unroll
    for (int k = 0; k < 8; k++)
        *(float4*)&acc[(k * 256 + tid) * 4] = make_float4(0.f, 0.f, 0.f, 0.f);

    if (end - start <= CAP) {
        // ---- sorted path: single-writer STS, no atomics on features ----
        cnt[2 * tid]     = 0;
        cnt[2 * tid + 1] = 0;
        __syncthreads();

        for (int t = start + tid; t < end; t += 256)
            atomicAdd(&cnt[g_order[t] & 511u], 1);
        __syncthreads();

        const int a = cnt[2 * tid];
        const int b = cnt[2 * tid + 1];
        const int sum = a + b;
        scrat[tid] = sum;
        __syncthreads();
        for (int off = 1; off < 256; off <<= 1) {
            int x = (tid >= off) ? scrat[tid - off] : 0;
            __syncthreads();
            scrat[tid] += x;
            __syncthreads();
        }
        const int excl = scrat[tid] - sum;
        soff[2 * tid]     = excl;
        soff[2 * tid + 1] = excl + a;
        cnt[2 * tid]      = excl;
        cnt[2 * tid + 1]  = excl + a;
        if (tid == 255) soff[512] = scrat[255];
        __syncthreads();

        for (int t = start + tid; t < end; t += 256) {
            const unsigned pay = g_order[t];
            int pos = atomicAdd(&cnt[pay & 511u], 1);
            spay[pos] = pay;
        }
        __syncthreads();

        #pragma unroll
        for (int vv = 0; vv < 2; vv++) {
            const int v = tid + vv * 256;
            const int s = soff[v];
            const int e = soff[v + 1];
            if (s == e) continue;

            float a16[16];
            #pragma unroll
            for (int f = 0; f < 16; f++) a16[f] = 0.f;

            for (int t = s; t < e; t++) {
                const unsigned i = spay[t] >> 9;
                const float4* fp = feats + (size_t)i * 4;
                float4 f0 = __ldg(fp + 0);
                float4 f1 = __ldg(fp + 1);
                float4 f2 = __ldg(fp + 2);
                float4 f3 = __ldg(fp + 3);
                a16[0]  += f0.x; a16[1]  += f0.y; a16[2]  += f0.z; a16[3]  += f0.w;
                a16[4]  += f1.x; a16[5]  += f1.y; a16[6]  += f1.z; a16[7]  += f1.w;
                a16[8]  += f2.x; a16[9]  += f2.y; a16[10] += f2.z; a16[11] += f2.w;
                a16[12] += f3.x; a16[13] += f3.y; a16[14] += f3.z; a16[15] += f3.w;
            }
            #pragma unroll
            for (int f = 0; f < 16; f++) acc[f * 512 + v] = a16[f];
        }
    } else {
        // ---- fallback: R3 atomic path for oversized bins ----
        __syncthreads();
        for (int t = start + tid; t < end; t += 256) {
            const unsigned pay   = g_order[t];
            const unsigned local = pay & 511u;
            const unsigned i     = pay >> 9;
            const float4* fp = feats + (size_t)i * 4;
            float4 f0 = __ldg(fp + 0);
            float4 f1 = __ldg(fp + 1);
            float4 f2 = __ldg(fp + 2);
            float4 f3 = __ldg(fp + 3);
            float v[16] = { f0.x, f0.y, f0.z, f0.w,
                            f1.x, f1.y, f1.z, f1.w,
                            f2.x, f2.y, f2.z, f2.w,
                            f3.x, f3.y, f3.z, f3.w };
            #pragma unroll
            for (int f = 0; f < FEATS; f++)
                atomicAdd(&acc[f * 512 + local], v[f]);
        }
    }
    __syncthreads();

    const unsigned b = bin >> 12;
    float* base = out + (size_t)b * FEATS * VOL + ((size_t)(bin & 4095u) << 9);

    #pragma unroll
    for (int k = 0; k < 8; k++) {
        const int idx = k * 256 + tid;
        const int f = idx >> 7;
        const int w = idx & 127;
        float4 val = *(const float4*)&acc[f * 512 + w * 4];
        *(float4*)(base + (size_t)f * VOL + (size_t)w * 4) = val;
    }
}

extern "C" void kernel_launch(void* const* d_in, const int* in_sizes, int n_in,
                              void* d_out, int out_size)
{
    const int4*   coords = (const int4*)d_in[0];
    const float4* feats  = (const float4*)d_in[1];
    float*        out    = (float*)d_out;

    const int n = in_sizes[0] / 4;

    zero_bins_kernel<<<(NBINS + 255) / 256, 256>>>();
    hist_kernel<<<1024, 256>>>(coords, n);
    scan_kernel<<<1, 1024>>>();
    reorder_kernel<<<1024, 256>>>(n);
    scatter_kernel<<<NBINS, 256>>>(feats, out);
}

// round 7
// speedup vs baseline: 1.4285x; 1.2767x over previous
#include <cuda_runtime.h>
#include <cstdint>

// SparseToDense: counting sort to 16K (b,x,y/4) bins. Scatter is point-parallel;
// voxels with a single point use plain STS (zeroed smem => store == sum),
// multi-point voxels (~17%) use smem atomics. Rank-from-histogram removes all
// atomics from the reorder step.
// out[b][f][x][y][z] += feats[n][f], out = (4,16,128,128,128) f32.

#define VOL    (128 * 128 * 128)
#define FEATS  16
#define NBINS  16384            // (b, x, y/4)
#define NMAX   2100000

__device__ int g_bins[NBINS];
__device__ int g_start[NBINS + 1];
__device__ uint2 g_pinfo[NMAX];      // .x = (bin<<9)|local (~0u invalid), .y = rank in bin
__device__ unsigned g_order[NMAX];   // packed: (point_idx << 9) | local_voxel

__device__ __forceinline__ bool decode(const int4 c, unsigned& bin, unsigned& local)
{
    const unsigned x = (unsigned)c.y;
    const unsigned y = (unsigned)c.z;
    const unsigned z = (unsigned)c.w;
    if ((x >= 128u) | (y >= 128u) | (z >= 128u)) return false;
    bin   = ((((unsigned)c.x << 7) | x) << 5) | (y >> 2);
    local = ((y & 3u) << 7) | z;
    return true;
}

__global__ void zero_bins_kernel()
{
    int i = blockIdx.x * blockDim.x + threadIdx.x;
    if (i < NBINS) g_bins[i] = 0;
}

// Histogram; atomicAdd return value doubles as the point's rank within its bin.
__global__ void __launch_bounds__(256)
hist_kernel(const int4* __restrict__ coords, int n)
{
    for (int i = blockIdx.x * blockDim.x + threadIdx.x; i < n;
         i += gridDim.x * blockDim.x) {
        unsigned bin, local;
        if (decode(__ldg(&coords[i]), bin, local)) {
            unsigned rank = atomicAdd(&g_bins[bin], 1);
            g_pinfo[i] = make_uint2((bin << 9) | local, rank);
        } else {
            g_pinfo[i] = make_uint2(~0u, 0u);
        }
    }
}

__global__ void scan_kernel()
{
    __shared__ int s[1024];
    const int t = threadIdx.x;
    int v[16];
    int sum = 0;
    #pragma unroll
    for (int k = 0; k < 16; k++) { v[k] = g_bins[t * 16 + k]; sum += v[k]; }
    s[t] = sum;
    __syncthreads();
    for (int off = 1; off < 1024; off <<= 1) {
        int x = (t >= off) ? s[t - off] : 0;
        __syncthreads();
        s[t] += x;
        __syncthreads();
    }
    int run = s[t] - sum;
    #pragma unroll
    for (int k = 0; k < 16; k++) {
        g_start[t * 16 + k] = run;
        run += v[k];
    }
    if (t == 1023) g_start[NBINS] = run;
}

// No atomics: slot = g_start[bin] + rank.
__global__ void __launch_bounds__(256)
reorder_kernel(int n)
{
    for (int i = blockIdx.x * blockDim.x + threadIdx.x; i < n;
         i += gridDim.x * blockDim.x) {
        const uint2 p = g_pinfo[i];
        if (p.x != ~0u) {
            const unsigned bin = p.x >> 9;
            g_order[g_start[bin] + p.y] = ((unsigned)i << 9) | (p.x & 511u);
        }
    }
}

__global__ void __launch_bounds__(256)
scatter_kernel(const float4* __restrict__ feats, float* __restrict__ out)
{
    __shared__ float acc[FEATS * 512];   // [f][512]
    __shared__ int   cnt[512];

    const unsigned bin = blockIdx.x;
    const int tid = threadIdx.x;
    const int start = g_start[bin];
    const int end   = g_start[bin + 1];

    #pragma unroll
    for (int k = 0; k < 8; k++)
        *(float4*)&acc[(k * 256 + tid) * 4] = make_float4(0.f, 0.f, 0.f, 0.f);
    cnt[2 * tid]     = 0;
    cnt[2 * tid + 1] = 0;
    __syncthreads();

    // Pass 1: per-voxel occupancy count (1 smem atomic per point)
    for (int t = start + tid; t < end; t += 256)
        atomicAdd(&cnt[g_order[t] & 511u], 1);
    __syncthreads();

    // Pass 2: singles store plainly (sole writer into zeroed smem);
    //         multi-occupancy voxels use smem atomics.
    for (int t = start + tid; t < end; t += 256) {
        const unsigned pay   = g_order[t];
        const unsigned local = pay & 511u;
        const unsigned i     = pay >> 9;

        const float4* fp = feats + (size_t)i * 4;
        float4 f0 = __ldg(fp + 0);
        float4 f1 = __ldg(fp + 1);
        float4 f2 = __ldg(fp + 2);
        float4 f3 = __ldg(fp + 3);
        float v[16] = { f0.x, f0.y, f0.z, f0.w,
                        f1.x, f1.y, f1.z, f1.w,
                        f2.x, f2.y, f2.z, f2.w,
                        f3.x, f3.y, f3.z, f3.w };

        if (cnt[local] == 1) {
            #pragma unroll
            for (int f = 0; f < FEATS; f++)
                acc[f * 512 + local] = v[f];
        } else {
            #pragma unroll
            for (int f = 0; f < FEATS; f++)
                atomicAdd(&acc[f * 512 + local], v[f]);
        }
    }
    __syncthreads();

    const unsigned b = bin >> 12;
    float* base = out + (size_t)b * FEATS * VOL + ((size_t)(bin & 4095u) << 9);

    #pragma unroll
    for (int k = 0; k < 8; k++) {
        const int idx = k * 256 + tid;
        const int f = idx >> 7;
        const int w = idx & 127;
        float4 val = *(const float4*)&acc[f * 512 + w * 4];
        *(float4*)(base + (size_t)f * VOL + (size_t)w * 4) = val;
    }
}

extern "C" void kernel_launch(void* const* d_in, const int* in_sizes, int n_in,
                              void* d_out, int out_size)
{
    const int4*   coords = (const int4*)d_in[0];
    const float4* feats  = (const float4*)d_in[1];
    float*        out    = (float*)d_out;

    const int n = in_sizes[0] / 4;

    zero_bins_kernel<<<(NBINS + 255) / 256, 256>>>();
    hist_kernel<<<1024, 256>>>(coords, n);
    scan_kernel<<<1, 1024>>>();
    reorder_kernel<<<1024, 256>>>(n);
    scatter_kernel<<<NBINS, 256>>>(feats, out);
}

// round 8
// speedup vs baseline: 1.4545x; 1.0182x over previous
#include <cuda_runtime.h>
#include <cstdint>

// SparseToDense: counting sort to 16K (b,x,y/4) bins. Scatter is a single
// fused point-parallel pass: feat loads issued before the count barrier so the
// random-gather latency overlaps the occupancy count. Singles use plain STS,
// multi-occupancy voxels (~17%) use smem atomics.
// out[b][f][x][y][z] += feats[n][f], out = (4,16,128,128,128) f32.

#define VOL    (128 * 128 * 128)
#define FEATS  16
#define NBINS  16384            // (b, x, y/4)
#define NMAX   2100000

__device__ int g_bins[NBINS];
__device__ int g_start[NBINS + 1];
__device__ unsigned g_pinfo[NMAX];   // bin:14 | local:9 | rank:9 ; ~0u = invalid
__device__ unsigned g_order[NMAX];   // (point_idx << 9) | local_voxel

__device__ __forceinline__ bool decode(const int4 c, unsigned& bin, unsigned& local)
{
    const unsigned x = (unsigned)c.y;
    const unsigned y = (unsigned)c.z;
    const unsigned z = (unsigned)c.w;
    if ((x >= 128u) | (y >= 128u) | (z >= 128u)) return false;
    bin   = ((((unsigned)c.x << 7) | x) << 5) | (y >> 2);
    local = ((y & 3u) << 7) | z;
    return true;
}

__global__ void zero_bins_kernel()
{
    int i = blockIdx.x * blockDim.x + threadIdx.x;
    if (i < NBINS) g_bins[i] = 0;
}

// Histogram; atomicAdd return value is the point's rank within its bin.
__global__ void __launch_bounds__(256)
hist_kernel(const int4* __restrict__ coords, int n)
{
    for (int i = blockIdx.x * blockDim.x + threadIdx.x; i < n;
         i += gridDim.x * blockDim.x) {
        unsigned bin, local;
        if (decode(__ldg(&coords[i]), bin, local)) {
            unsigned rank = atomicAdd(&g_bins[bin], 1);   // rank < 512 always
            g_pinfo[i] = (bin << 18) | (local << 9) | rank;
        } else {
            g_pinfo[i] = ~0u;
        }
    }
}

__global__ void scan_kernel()
{
    __shared__ int s[1024];
    const int t = threadIdx.x;
    int v[16];
    int sum = 0;
    #pragma unroll
    for (int k = 0; k < 16; k++) { v[k] = g_bins[t * 16 + k]; sum += v[k]; }
    s[t] = sum;
    __syncthreads();
    for (int off = 1; off < 1024; off <<= 1) {
        int x = (t >= off) ? s[t - off] : 0;
        __syncthreads();
        s[t] += x;
        __syncthreads();
    }
    int run = s[t] - sum;
    #pragma unroll
    for (int k = 0; k < 16; k++) {
        g_start[t * 16 + k] = run;
        run += v[k];
    }
    if (t == 1023) g_start[NBINS] = run;
}

// No atomics: slot = g_start[bin] + rank.
__global__ void __launch_bounds__(256)
reorder_kernel(int n)
{
    for (int i = blockIdx.x * blockDim.x + threadIdx.x; i < n;
         i += gridDim.x * blockDim.x) {
        const unsigned p = g_pinfo[i];
        if (p != ~0u) {
            const unsigned bin   = p >> 18;
            const unsigned local = (p >> 9) & 511u;
            const unsigned rank  = p & 511u;
            g_order[g_start[bin] + rank] = ((unsigned)i << 9) | local;
        }
    }
}

__global__ void __launch_bounds__(256)
scatter_kernel(const float4* __restrict__ feats, float* __restrict__ out)
{
    __shared__ float acc[FEATS * 512];   // [f][512]
    __shared__ int   cnt[512];

    const unsigned bin = blockIdx.x;
    const int tid = threadIdx.x;
    const int start = g_start[bin];
    const int end   = g_start[bin + 1];
    const int npts  = end - start;

    #pragma unroll
    for (int k = 0; k < 8; k++)
        *(float4*)&acc[(k * 256 + tid) * 4] = make_float4(0.f, 0.f, 0.f, 0.f);
    cnt[2 * tid]     = 0;
    cnt[2 * tid + 1] = 0;

    if (npts <= 256) {
        // ---- fused single-pass: loads in flight across the count barrier ----
        const int t = start + tid;
        const bool have = (t < end);
        unsigned pay = 0, local = 0;
        float4 f0, f1, f2, f3;
        if (have) {
            pay   = g_order[t];
            local = pay & 511u;
            const float4* fp = feats + (size_t)(pay >> 9) * 4;
            f0 = __ldg(fp + 0);          // all four issued up-front; latency
            f1 = __ldg(fp + 1);          // overlaps the count pass + barrier
            f2 = __ldg(fp + 2);
            f3 = __ldg(fp + 3);
        }
        __syncthreads();                 // cnt[] zeros visible
        if (have) atomicAdd(&cnt[local], 1);
        __syncthreads();

        if (have) {
            float v[16] = { f0.x, f0.y, f0.z, f0.w,
                            f1.x, f1.y, f1.z, f1.w,
                            f2.x, f2.y, f2.z, f2.w,
                            f3.x, f3.y, f3.z, f3.w };
            if (cnt[local] == 1) {
                #pragma unroll
                for (int f = 0; f < FEATS; f++)
                    acc[f * 512 + local] = v[f];
            } else {
                #pragma unroll
                for (int f = 0; f < FEATS; f++)
                    atomicAdd(&acc[f * 512 + local], v[f]);
            }
        }
    } else {
        // ---- fallback two-pass (statistically unreachable; kept for safety) ----
        __syncthreads();
        for (int t = start + tid; t < end; t += 256)
            atomicAdd(&cnt[g_order[t] & 511u], 1);
        __syncthreads();
        for (int t = start + tid; t < end; t += 256) {
            const unsigned pay   = g_order[t];
            const unsigned local = pay & 511u;
            const float4* fp = feats + (size_t)(pay >> 9) * 4;
            float4 f0 = __ldg(fp + 0);
            float4 f1 = __ldg(fp + 1);
            float4 f2 = __ldg(fp + 2);
            float4 f3 = __ldg(fp + 3);
            float v[16] = { f0.x, f0.y, f0.z, f0.w,
                            f1.x, f1.y, f1.z, f1.w,
                            f2.x, f2.y, f2.z, f2.w,
                            f3.x, f3.y, f3.z, f3.w };
            if (cnt[local] == 1) {
                #pragma unroll
                for (int f = 0; f < FEATS; f++)
                    acc[f * 512 + local] = v[f];
            } else {
                #pragma unroll
                for (int f = 0; f < FEATS; f++)
                    atomicAdd(&acc[f * 512 + local], v[f]);
            }
        }
    }
    __syncthreads();

    const unsigned b = bin >> 12;
    float* base = out + (size_t)b * FEATS * VOL + ((size_t)(bin & 4095u) << 9);

    #pragma unroll
    for (int k = 0; k < 8; k++) {
        const int idx = k * 256 + tid;
        const int f = idx >> 7;
        const int w = idx & 127;
        float4 val = *(const float4*)&acc[f * 512 + w * 4];
        *(float4*)(base + (size_t)f * VOL + (size_t)w * 4) = val;
    }
}

extern "C" void kernel_launch(void* const* d_in, const int* in_sizes, int n_in,
                              void* d_out, int out_size)
{
    const int4*   coords = (const int4*)d_in[0];
    const float4* feats  = (const float4*)d_in[1];
    float*        out    = (float*)d_out;

    const int n = in_sizes[0] / 4;

    zero_bins_kernel<<<(NBINS + 255) / 256, 256>>>();
    hist_kernel<<<1024, 256>>>(coords, n);
    scan_kernel<<<1, 1024>>>();
    reorder_kernel<<<1024, 256>>>(n);
    scatter_kernel<<<NBINS, 256>>>(feats, out);
}

// round 10
// speedup vs baseline: 1.4547x; 1.0001x over previous
#include <cuda_runtime.h>
#include <cstdint>

// SparseToDense: counting sort to 16K (b,x,y/4) bins. Scatter is a fused
// point-parallel pass (gather latency overlaps the occupancy count); singles
// use plain STS, multi-occupancy voxels use smem atomics. Writeback goes
// through cp.async.bulk (TMA engine) instead of per-thread STG.128 to take
// the 512MB store off the LSU issue path.
// out[b][f][x][y][z] += feats[n][f], out = (4,16,128,128,128) f32.

#define VOL    (128 * 128 * 128)
#define FEATS  16
#define NBINS  16384            // (b, x, y/4)
#define NMAX   2100000

__device__ int g_bins[NBINS];
__device__ int g_start[NBINS + 1];
__device__ unsigned g_pinfo[NMAX];   // bin:14 | local:9 | rank:9 ; ~0u = invalid
__device__ unsigned g_order[NMAX];   // (point_idx << 9) | local_voxel

__device__ __forceinline__ bool decode(const int4 c, unsigned& bin, unsigned& local)
{
    const unsigned x = (unsigned)c.y;
    const unsigned y = (unsigned)c.z;
    const unsigned z = (unsigned)c.w;
    if ((x >= 128u) | (y >= 128u) | (z >= 128u)) return false;
    bin   = ((((unsigned)c.x << 7) | x) << 5) | (y >> 2);
    local = ((y & 3u) << 7) | z;
    return true;
}

__global__ void zero_bins_kernel()
{
    int i = blockIdx.x * blockDim.x + threadIdx.x;
    if (i < NBINS) g_bins[i] = 0;
}

// Histogram; atomicAdd return value is the point's rank within its bin.
__global__ void __launch_bounds__(256)
hist_kernel(const int4* __restrict__ coords, int n)
{
    for (int i = blockIdx.x * blockDim.x + threadIdx.x; i < n;
         i += gridDim.x * blockDim.x) {
        unsigned bin, local;
        if (decode(__ldg(&coords[i]), bin, local)) {
            unsigned rank = atomicAdd(&g_bins[bin], 1);   // rank < 512 always
            g_pinfo[i] = (bin << 18) | (local << 9) | rank;
        } else {
            g_pinfo[i] = ~0u;
        }
    }
}

__global__ void scan_kernel()
{
    __shared__ int s[1024];
    const int t = threadIdx.x;
    int v[16];
    int sum = 0;
    #pragma unroll
    for (int k = 0; k < 16; k++) { v[k] = g_bins[t * 16 + k]; sum += v[k]; }
    s[t] = sum;
    __syncthreads();
    for (int off = 1; off < 1024; off <<= 1) {
        int x = (t >= off) ? s[t - off] : 0;
        __syncthreads();
        s[t] += x;
        __syncthreads();
    }
    int run = s[t] - sum;
    #pragma unroll
    for (int k = 0; k < 16; k++) {
        g_start[t * 16 + k] = run;
        run += v[k];
    }
    if (t == 1023) g_start[NBINS] = run;
}

// No atomics: slot = g_start[bin] + rank.
__global__ void __launch_bounds__(256)
reorder_kernel(int n)
{
    for (int i = blockIdx.x * blockDim.x + threadIdx.x; i < n;
         i += gridDim.x * blockDim.x) {
        const unsigned p = g_pinfo[i];
        if (p != ~0u) {
            const unsigned bin   = p >> 18;
            const unsigned local = (p >> 9) & 511u;
            const unsigned rank  = p & 511u;
            g_order[g_start[bin] + rank] = ((unsigned)i << 9) | local;
        }
    }
}

__global__ void __launch_bounds__(256)
scatter_kernel(const float4* __restrict__ feats, float* __restrict__ out)
{
    __shared__ __align__(16) float acc[FEATS * 512];   // [f][512], 2KB per f
    __shared__ int cnt[512];

    const unsigned bin = blockIdx.x;
    const int tid = threadIdx.x;
    const int start = g_start[bin];
    const int end   = g_start[bin + 1];
    const int npts  = end - start;

    #pragma unroll
    for (int k = 0; k < 8; k++)
        *(float4*)&acc[(k * 256 + tid) * 4] = make_float4(0.f, 0.f, 0.f, 0.f);
    cnt[2 * tid]     = 0;
    cnt[2 * tid + 1] = 0;

    if (npts <= 256) {
        // ---- fused single-pass: loads in flight across the count barrier ----
        const int t = start + tid;
        const bool have = (t < end);
        unsigned local = 0;
        float4 f0, f1, f2, f3;
        if (have) {
            const unsigned pay = g_order[t];
            local = pay & 511u;
            const float4* fp = feats + (size_t)(pay >> 9) * 4;
            f0 = __ldg(fp + 0);          // issued up-front; latency overlaps
            f1 = __ldg(fp + 1);          // the count pass + barriers
            f2 = __ldg(fp + 2);
            f3 = __ldg(fp + 3);
        }
        __syncthreads();                 // cnt[] zeros visible
        if (have) atomicAdd(&cnt[local], 1);
        __syncthreads();

        if (have) {
            float v[16] = { f0.x, f0.y, f0.z, f0.w,
                            f1.x, f1.y, f1.z, f1.w,
                            f2.x, f2.y, f2.z, f2.w,
                            f3.x, f3.y, f3.z, f3.w };
            if (cnt[local] == 1) {
                #pragma unroll
                for (int f = 0; f < FEATS; f++)
                    acc[f * 512 + local] = v[f];
            } else {
                #pragma unroll
                for (int f = 0; f < FEATS; f++)
                    atomicAdd(&acc[f * 512 + local], v[f]);
            }
        }
    } else {
        // ---- fallback two-pass (statistically unreachable; kept for safety) ----
        __syncthreads();
        for (int t = start + tid; t < end; t += 256)
            atomicAdd(&cnt[g_order[t] & 511u], 1);
        __syncthreads();
        for (int t = start + tid; t < end; t += 256) {
            const unsigned pay   = g_order[t];
            const unsigned local = pay & 511u;
            const float4* fp = feats + (size_t)(pay >> 9) * 4;
            float4 f0 = __ldg(fp + 0);
            float4 f1 = __ldg(fp + 1);
            float4 f2 = __ldg(fp + 2);
            float4 f3 = __ldg(fp + 3);
            float v[16] = { f0.x, f0.y, f0.z, f0.w,
                            f1.x, f1.y, f1.z, f1.w,
                            f2.x, f2.y, f2.z, f2.w,
                            f3.x, f3.y, f3.z, f3.w };
            if (cnt[local] == 1) {
                #pragma unroll
                for (int f = 0; f < FEATS; f++)
                    acc[f * 512 + local] = v[f];
            } else {
                #pragma unroll
                for (int f = 0; f < FEATS; f++)
                    atomicAdd(&acc[f * 512 + local], v[f]);
            }
        }
    }
    __syncthreads();

    // ---- bulk async writeback: 16 contiguous 2KB chunks, TMA engine ----
    if (tid == 0) {
        asm volatile("fence.proxy.async.shared::cta;" ::: "memory");

        const unsigned b = bin >> 12;
        float* base = out + (size_t)b * FEATS * VOL + ((size_t)(bin & 4095u) << 9);

        uint32_t sa;
        asm("{ .reg .u64 t; cvta.to.shared.u64 t, %1; cvt.u32.u64 %0, t; }"
            : "=r"(sa) : "l"(acc));

        #pragma unroll
        for (int f = 0; f < FEATS; f++) {
            asm volatile(
                "cp.async.bulk.global.shared::cta.bulk_group [%0], [%1], %2;"
                :: "l"(base + (size_t)f * VOL),
                   "r"(sa + f * 512 * 4),
                   "n"(512 * 4)
                : "memory");
        }
        asm volatile("cp.async.bulk.commit_group;" ::: "memory");
        asm volatile("cp.async.bulk.wait_group.read 0;" ::: "memory");
    }
}

extern "C" void kernel_launch(void* const* d_in, const int* in_sizes, int n_in,
                              void* d_out, int out_size)
{
    const int4*   coords = (const int4*)d_in[0];
    const float4* feats  = (const float4*)d_in[1];
    float*        out    = (float*)d_out;

    const int n = in_sizes[0] / 4;

    zero_bins_kernel<<<(NBINS + 255) / 256, 256>>>();
    hist_kernel<<<1024, 256>>>(coords, n);
    scan_kernel<<<1, 1024>>>();
    reorder_kernel<<<1024, 256>>>(n);
    scatter_kernel<<<NBINS, 256>>>(feats, out);
}